// round 17
// baseline (speedup 1.0000x reference)
#include <cuda_runtime.h>

#define B_  4
#define L_  1024
#define D_  512
#define H_  8
#define DK_ 64

// ---------------- scratch (no allocations allowed) ----------------
__device__ float g_Q [B_*L_*D_];
__device__ float g_K [B_*L_*D_];
__device__ float g_V [B_*L_*D_];
__device__ float g_QP[B_*L_*D_];
__device__ float g_KP[B_*L_*D_];
__device__ float g_AV[B_*L_*D_];
__device__ float g_g [B_*L_];
__device__ float g_EW[B_*L_*L_];    // exp(1 - m), head-independent

// ---------------- tf32 helpers ----------------
__device__ __forceinline__ float tf32r(float x) {
    unsigned u;
    asm("cvt.rna.tf32.f32 %0, %1;" : "=r"(u) : "f"(x));
    return __uint_as_float(u);
}
__device__ __forceinline__ void mma_tf32(float c[4],
    unsigned a0, unsigned a1, unsigned a2, unsigned a3,
    unsigned b0, unsigned b1)
{
    asm("mma.sync.aligned.m16n8k8.row.col.f32.tf32.tf32.f32 "
        "{%0,%1,%2,%3},{%4,%5,%6,%7},{%8,%9},{%0,%1,%2,%3};"
        : "+f"(c[0]), "+f"(c[1]), "+f"(c[2]), "+f"(c[3])
        : "r"(a0), "r"(a1), "r"(a2), "r"(a3), "r"(b0), "r"(b1));
}
#define FU(x) __float_as_uint(x)

__device__ __forceinline__ void split_tf32(float x, unsigned& hi, unsigned& lo) {
    float h = tf32r(x);
    hi = FU(h);
    lo = FU(tf32r(x - h));
}

// =================================================================
// tf32 MMA NN GEMM: C[M,N] = A[M,512] @ W[512,N] + bias (row-major)
// 128x128 tile, BK=16, 256 threads = 8 warps (2m x 4n), warp 64x32.
// =================================================================
__device__ __forceinline__ void gemm_mma_nn(
    const float* __restrict__ A, const float* __restrict__ W,
    const float* __restrict__ bias, float* __restrict__ C,
    float As[128][20], float Ws[16][136])
{
    const int tid  = threadIdx.x;
    const int lane = tid & 31, warp = tid >> 5;
    const int wm = (warp >> 2) * 64;        // 0 / 64
    const int wn = (warp & 3) * 32;         // 0..96
    const int gID = lane >> 2, tig = lane & 3;
    const int m0 = blockIdx.y * 128, n0 = blockIdx.x * 128;

    float acc[4][4][4] = {};

    for (int k0 = 0; k0 < 512; k0 += 16) {
        #pragma unroll
        for (int l = 0; l < 2; l++) {
            int idx = tid + l * 256;
            int r = idx & 127;
            int c = (idx >> 7) * 4;
            float4 v = *(const float4*)(A + (size_t)(m0 + r) * 512 + k0 + c);
            As[r][c+0] = tf32r(v.x); As[r][c+1] = tf32r(v.y);
            As[r][c+2] = tf32r(v.z); As[r][c+3] = tf32r(v.w);
        }
        #pragma unroll
        for (int l = 0; l < 2; l++) {
            int idx = tid + l * 256;
            int r = idx >> 5;                // 0..15
            int c = (idx & 31) * 4;
            float4 v = *(const float4*)(W + (size_t)(k0 + r) * 512 + n0 + c);
            Ws[r][c+0] = tf32r(v.x); Ws[r][c+1] = tf32r(v.y);
            Ws[r][c+2] = tf32r(v.z); Ws[r][c+3] = tf32r(v.w);
        }
        __syncthreads();

        #pragma unroll
        for (int kk = 0; kk < 16; kk += 8) {
            unsigned af[4][4], bf[4][2];
            #pragma unroll
            for (int i = 0; i < 4; i++) {
                int r = wm + i * 16 + gID;
                af[i][0] = FU(As[r    ][kk + tig    ]);
                af[i][1] = FU(As[r + 8][kk + tig    ]);
                af[i][2] = FU(As[r    ][kk + tig + 4]);
                af[i][3] = FU(As[r + 8][kk + tig + 4]);
            }
            #pragma unroll
            for (int j = 0; j < 4; j++) {
                int cn = wn + j * 8 + gID;
                bf[j][0] = FU(Ws[kk + tig    ][cn]);
                bf[j][1] = FU(Ws[kk + tig + 4][cn]);
            }
            #pragma unroll
            for (int i = 0; i < 4; i++)
                #pragma unroll
                for (int j = 0; j < 4; j++)
                    mma_tf32(acc[i][j], af[i][0], af[i][1], af[i][2], af[i][3],
                             bf[j][0], bf[j][1]);
        }
        __syncthreads();
    }

    #pragma unroll
    for (int i = 0; i < 4; i++) {
        #pragma unroll
        for (int j = 0; j < 4; j++) {
            int row = m0 + wm + i * 16 + gID;
            int col = n0 + wn + j * 8 + tig * 2;
            float bx = bias[col], by = bias[col + 1];
            *(float2*)(C + (size_t)row * 512 + col) =
                make_float2(acc[i][j][0] + bx, acc[i][j][1] + by);
            *(float2*)(C + (size_t)(row + 8) * 512 + col) =
                make_float2(acc[i][j][2] + bx, acc[i][j][3] + by);
        }
    }
}

struct Proj5 {
    const float* A[5];
    const float* W[5];
    const float* bias[5];
    float*       C[5];
};

__global__ __launch_bounds__(256) void proj5_kernel(Proj5 p)
{
    __shared__ float As[128][20];
    __shared__ float Ws[16][136];
    const int z = blockIdx.z;
    gemm_mma_nn(p.A[z], p.W[z], p.bias[z], p.C[z], As, Ws);
}

__global__ __launch_bounds__(256) void dense_kernel(
    const float* __restrict__ A, const float* __restrict__ W,
    const float* __restrict__ bias, float* __restrict__ C)
{
    __shared__ float As[128][20];
    __shared__ float Ws[16][136];
    gemm_mma_nn(A, W, bias, C, As, Ws);
}

// =================================================================
// m kernel (tf32 MMA NT): m = sigmoid( (QP @ KP^T) / sqrt(512) )
// Also writes EW = exp(1 - m) to scratch (reused by all 8 heads).
// =================================================================
__global__ __launch_bounds__(256) void m_kernel(
    const float* __restrict__ QP, const float* __restrict__ KP,
    float* __restrict__ Mout, float* __restrict__ EW)
{
    const int bz = blockIdx.z;
    const float* A  = QP + (size_t)bz * L_ * D_;
    const float* Bp = KP + (size_t)bz * L_ * D_;
    float* C = Mout + (size_t)bz * L_ * L_;
    float* E = EW   + (size_t)bz * L_ * L_;

    __shared__ float As[128][20];
    __shared__ float Bs[128][20];

    const int tid  = threadIdx.x;
    const int lane = tid & 31, warp = tid >> 5;
    const int wm = (warp >> 2) * 64;
    const int wn = (warp & 3) * 32;
    const int gID = lane >> 2, tig = lane & 3;
    const int m0 = blockIdx.y * 128, n0 = blockIdx.x * 128;

    float acc[4][4][4] = {};

    for (int k0 = 0; k0 < 512; k0 += 16) {
        #pragma unroll
        for (int l = 0; l < 2; l++) {
            int idx = tid + l * 256;
            int r = idx & 127;
            int c = (idx >> 7) * 4;
            float4 v = *(const float4*)(A + (size_t)(m0 + r) * 512 + k0 + c);
            As[r][c+0] = tf32r(v.x); As[r][c+1] = tf32r(v.y);
            As[r][c+2] = tf32r(v.z); As[r][c+3] = tf32r(v.w);
            float4 w = *(const float4*)(Bp + (size_t)(n0 + r) * 512 + k0 + c);
            Bs[r][c+0] = tf32r(w.x); Bs[r][c+1] = tf32r(w.y);
            Bs[r][c+2] = tf32r(w.z); Bs[r][c+3] = tf32r(w.w);
        }
        __syncthreads();

        #pragma unroll
        for (int kk = 0; kk < 16; kk += 8) {
            unsigned af[4][4], bf[4][2];
            #pragma unroll
            for (int i = 0; i < 4; i++) {
                int r = wm + i * 16 + gID;
                af[i][0] = FU(As[r    ][kk + tig    ]);
                af[i][1] = FU(As[r + 8][kk + tig    ]);
                af[i][2] = FU(As[r    ][kk + tig + 4]);
                af[i][3] = FU(As[r + 8][kk + tig + 4]);
            }
            #pragma unroll
            for (int j = 0; j < 4; j++) {
                int rn = wn + j * 8 + gID;
                bf[j][0] = FU(Bs[rn][kk + tig    ]);
                bf[j][1] = FU(Bs[rn][kk + tig + 4]);
            }
            #pragma unroll
            for (int i = 0; i < 4; i++)
                #pragma unroll
                for (int j = 0; j < 4; j++)
                    mma_tf32(acc[i][j], af[i][0], af[i][1], af[i][2], af[i][3],
                             bf[j][0], bf[j][1]);
        }
        __syncthreads();
    }

    const float sc = 0.04419417382415922f;   // 1/sqrt(512)
    #pragma unroll
    for (int i = 0; i < 4; i++) {
        #pragma unroll
        for (int j = 0; j < 4; j++) {
            int row = m0 + wm + i * 16 + gID;
            int col = n0 + wn + j * 8 + tig * 2;
            float s0 = 1.0f / (1.0f + __expf(-acc[i][j][0] * sc));
            float s1 = 1.0f / (1.0f + __expf(-acc[i][j][1] * sc));
            float s2 = 1.0f / (1.0f + __expf(-acc[i][j][2] * sc));
            float s3 = 1.0f / (1.0f + __expf(-acc[i][j][3] * sc));
            *(float2*)(C + (size_t)row * L_ + col)       = make_float2(s0, s1);
            *(float2*)(C + (size_t)(row + 8) * L_ + col) = make_float2(s2, s3);
            *(float2*)(E + (size_t)row * L_ + col)       =
                make_float2(__expf(1.0f - s0), __expf(1.0f - s1));
            *(float2*)(E + (size_t)(row + 8) * L_ + col) =
                make_float2(__expf(1.0f - s2), __expf(1.0f - s3));
        }
    }
}

// =================================================================
// gate kernel: g = sigmoid(query @ gate_w + gate_b), one warp per row
// =================================================================
__global__ __launch_bounds__(256) void gate_kernel(
    const float* __restrict__ query, const float* __restrict__ gw,
    const float* __restrict__ gb, float* __restrict__ g)
{
    const int row  = blockIdx.x * 8 + (threadIdx.x >> 5);
    const int lane = threadIdx.x & 31;
    const float* q = query + (size_t)row * D_;
    float s = 0.f;
    #pragma unroll
    for (int k = lane; k < D_; k += 32) s += q[k] * gw[k];
    #pragma unroll
    for (int o = 16; o; o >>= 1) s += __shfl_xor_sync(0xffffffffu, s, o);
    if (lane == 0) g[row] = 1.0f / (1.0f + __expf(-(s + gb[0])));
}

// =================================================================
// Fused attention kernel: one block = (b, h, 32 q rows), 256 threads.
// Phase1: S = QK^T/8 via 3xTF32 MMA (fp32-accurate).
// Phase2: 2-pass unnormalized double softmax (EW precomputed).
// Phase3: O = P@V via 3xTF32 MMA, rowInv in epilogue.
// =================================================================
#define S_STRIDE 1028
#define QS_OFF   (32 * S_STRIDE)              // 32896
#define KS_OFF   (QS_OFF + 32 * 68)           // 35072
#define SMEM_FLOATS (KS_OFF + 256 * 68)       // 52480
#define ATTN_SMEM_BYTES (SMEM_FLOATS * 4)     // 209920

__global__ __launch_bounds__(256) void attn_kernel(
    const float* __restrict__ Q, const float* __restrict__ Kg,
    const float* __restrict__ Vg, const float* __restrict__ EWg,
    const float* __restrict__ gate, float* __restrict__ AV)
{
    extern __shared__ float sm[];
    float* S  = sm;              // [32][1028] scores / probs
    float* Qs = sm + QS_OFF;     // [32][68]   Q tile (row-major, padded)
    float* Ks = sm + KS_OFF;     // [256][68]  K chunk; later VT [64][132]
    __shared__ float rowInv[32];

    const int tid = threadIdx.x;
    const int lane = tid & 31, warp = tid >> 5;
    const int gID = lane >> 2, tig = lane & 3;
    const int b = blockIdx.z, h = blockIdx.y, q0 = blockIdx.x * 32;

    const float* Qb  = Q   + ((size_t)(b * L_ + q0)) * D_ + h * DK_;
    const float* Kb  = Kg  + (size_t)b * L_ * D_ + h * DK_;
    const float* Vb  = Vg  + (size_t)b * L_ * D_ + h * DK_;
    const float* EWb = EWg + (size_t)b * L_ * L_ + (size_t)q0 * L_;

    // ---- load Q tile [32][64] -> Qs[32][68] ----
    #pragma unroll
    for (int l = 0; l < 2; l++) {
        int idx = tid + l * 256;
        int r = idx & 31;
        int c = (idx >> 5) * 4;
        *(float4*)(Qs + r * 68 + c) = *(const float4*)(Qb + (size_t)r * D_ + c);
    }

    // ---- phase 1: S = (Q K^T) * 0.125, 3xTF32 MMA, k-chunks of 256 ----
    {
        const int wn = warp * 32;
        for (int k0 = 0; k0 < L_; k0 += 256) {
            #pragma unroll
            for (int l = 0; l < 16; l++) {
                int idx = tid + l * 256;
                int r = idx & 255;
                int c = (idx >> 8) * 4;
                *(float4*)(Ks + r * 68 + c) =
                    *(const float4*)(Kb + (size_t)(k0 + r) * D_ + c);
            }
            __syncthreads();

            float acc[2][4][4] = {};
            #pragma unroll
            for (int t = 0; t < 8; t++) {
                const int kk = t * 8;
                unsigned ahi[2][4], alo[2][4];
                #pragma unroll
                for (int i = 0; i < 2; i++) {
                    int r = i * 16 + gID;
                    split_tf32(Qs[(r    ) * 68 + kk + tig    ], ahi[i][0], alo[i][0]);
                    split_tf32(Qs[(r + 8) * 68 + kk + tig    ], ahi[i][1], alo[i][1]);
                    split_tf32(Qs[(r    ) * 68 + kk + tig + 4], ahi[i][2], alo[i][2]);
                    split_tf32(Qs[(r + 8) * 68 + kk + tig + 4], ahi[i][3], alo[i][3]);
                }
                #pragma unroll
                for (int j = 0; j < 4; j++) {
                    int n = wn + j * 8 + gID;
                    unsigned bh0, bl0, bh1, bl1;
                    split_tf32(Ks[n * 68 + kk + tig    ], bh0, bl0);
                    split_tf32(Ks[n * 68 + kk + tig + 4], bh1, bl1);
                    #pragma unroll
                    for (int i = 0; i < 2; i++) {
                        mma_tf32(acc[i][j], ahi[i][0], ahi[i][1], ahi[i][2], ahi[i][3], bh0, bh1);
                        mma_tf32(acc[i][j], ahi[i][0], ahi[i][1], ahi[i][2], ahi[i][3], bl0, bl1);
                        mma_tf32(acc[i][j], alo[i][0], alo[i][1], alo[i][2], alo[i][3], bh0, bh1);
                    }
                }
            }
            #pragma unroll
            for (int i = 0; i < 2; i++) {
                #pragma unroll
                for (int j = 0; j < 4; j++) {
                    int row = i * 16 + gID;
                    int col = k0 + wn + j * 8 + tig * 2;
                    *(float2*)(S + (size_t)row * S_STRIDE + col) =
                        make_float2(acc[i][j][0] * 0.125f, acc[i][j][1] * 0.125f);
                    *(float2*)(S + (size_t)(row + 8) * S_STRIDE + col) =
                        make_float2(acc[i][j][2] * 0.125f, acc[i][j][3] * 0.125f);
                }
            }
            __syncthreads();
        }
    }

    // ---- phase 2: 2-pass double softmax (unnormalized exp; EW given) ----
    {
        #pragma unroll
        for (int rr = 0; rr < 4; rr++) {
            const int r = warp * 4 + rr;
            float4* Srow4 = (float4*)(S + r * S_STRIDE);

            float sum = 0.f;
            for (int i = lane; i < 256; i += 32) {
                float4 v = Srow4[i];
                v.x = __expf(v.x); v.y = __expf(v.y);
                v.z = __expf(v.z); v.w = __expf(v.w);
                Srow4[i] = v;
                sum += v.x + v.y + v.z + v.w;
            }
            #pragma unroll
            for (int o = 16; o; o >>= 1) sum += __shfl_xor_sync(0xffffffffu, sum, o);
            const float inv = 1.0f / sum;

            const float gq  = gate[b * L_ + q0 + r];
            const float gq1 = 1.0f - gq;
            const float4* ew4 = (const float4*)(EWb + (size_t)r * L_);
            float s2 = 0.f;
            for (int i = lane; i < 256; i += 32) {
                float4 v = Srow4[i];
                float4 w = ew4[i];
                v.x = __expf(v.x * inv * (gq + gq1 * w.x));
                v.y = __expf(v.y * inv * (gq + gq1 * w.y));
                v.z = __expf(v.z * inv * (gq + gq1 * w.z));
                v.w = __expf(v.w * inv * (gq + gq1 * w.w));
                Srow4[i] = v;
                s2 += v.x + v.y + v.z + v.w;
            }
            #pragma unroll
            for (int o = 16; o; o >>= 1) s2 += __shfl_xor_sync(0xffffffffu, s2, o);
            if (lane == 0) rowInv[r] = 1.0f / s2;
        }
    }
    __syncthreads();

    // ---- phase 3: O = P @ V via 3xTF32 MMA, k-chunks of 128 ----
    {
        float* VT = Ks;                       // [64][132] V^T for this chunk
        const int wn = warp * 8;              // d columns per warp
        float acc[2][4] = {};

        for (int k0 = 0; k0 < L_; k0 += 128) {
            #pragma unroll
            for (int l = 0; l < 8; l++) {
                int idx = tid + l * 256;      // 2048 float4 = 128 rows x 16
                int r = idx & 127;
                int c = (idx >> 7) * 4;
                float4 v = *(const float4*)(Vb + (size_t)(k0 + r) * D_ + c);
                VT[(c+0)*132 + r] = v.x; VT[(c+1)*132 + r] = v.y;
                VT[(c+2)*132 + r] = v.z; VT[(c+3)*132 + r] = v.w;
            }
            __syncthreads();

            #pragma unroll
            for (int t = 0; t < 16; t++) {
                const int kk = t * 8;
                unsigned ahi[2][4], alo[2][4];
                #pragma unroll
                for (int i = 0; i < 2; i++) {
                    int r = i * 16 + gID;
                    split_tf32(S[(size_t)(r    ) * S_STRIDE + k0 + kk + tig    ], ahi[i][0], alo[i][0]);
                    split_tf32(S[(size_t)(r + 8) * S_STRIDE + k0 + kk + tig    ], ahi[i][1], alo[i][1]);
                    split_tf32(S[(size_t)(r    ) * S_STRIDE + k0 + kk + tig + 4], ahi[i][2], alo[i][2]);
                    split_tf32(S[(size_t)(r + 8) * S_STRIDE + k0 + kk + tig + 4], ahi[i][3], alo[i][3]);
                }
                int n = wn + gID;
                unsigned bh0, bl0, bh1, bl1;
                split_tf32(VT[n * 132 + kk + tig    ], bh0, bl0);
                split_tf32(VT[n * 132 + kk + tig + 4], bh1, bl1);
                #pragma unroll
                for (int i = 0; i < 2; i++) {
                    mma_tf32(acc[i], ahi[i][0], ahi[i][1], ahi[i][2], ahi[i][3], bh0, bh1);
                    mma_tf32(acc[i], ahi[i][0], ahi[i][1], ahi[i][2], ahi[i][3], bl0, bl1);
                    mma_tf32(acc[i], alo[i][0], alo[i][1], alo[i][2], alo[i][3], bh0, bh1);
                }
            }
            __syncthreads();
        }

        #pragma unroll
        for (int i = 0; i < 2; i++) {
            int r0 = i * 16 + gID;
            int r1 = r0 + 8;
            float i0 = rowInv[r0], i1 = rowInv[r1];
            *(float2*)(AV + ((size_t)(b * L_ + q0 + r0)) * D_ + h * DK_ + wn + tig * 2) =
                make_float2(acc[i][0] * i0, acc[i][1] * i0);
            *(float2*)(AV + ((size_t)(b * L_ + q0 + r1)) * D_ + h * DK_ + wn + tig * 2) =
                make_float2(acc[i][2] * i1, acc[i][3] * i1);
        }
    }
}

// =================================================================
// launcher
// =================================================================
extern "C" void kernel_launch(void* const* d_in, const int* in_sizes, int n_in,
                              void* d_out, int out_size)
{
    const float* query   = (const float*)d_in[0];
    const float* key     = (const float*)d_in[1];
    const float* value   = (const float*)d_in[2];
    const float* wq_w    = (const float*)d_in[3];
    const float* wq_b    = (const float*)d_in[4];
    const float* wk_w    = (const float*)d_in[5];
    const float* wk_b    = (const float*)d_in[6];
    const float* wv_w    = (const float*)d_in[7];
    const float* wv_b    = (const float*)d_in[8];
    const float* dense_w = (const float*)d_in[9];
    const float* dense_b = (const float*)d_in[10];
    const float* gate_w  = (const float*)d_in[11];
    const float* gate_b  = (const float*)d_in[12];
    const float* mp_wq_w = (const float*)d_in[13];
    const float* mp_wq_b = (const float*)d_in[14];
    const float* mp_wk_w = (const float*)d_in[15];
    const float* mp_wk_b = (const float*)d_in[16];

    float* out  = (float*)d_out;                    // (B, L, D)
    float* mout = out + (size_t)B_ * L_ * D_;       // (B, L, L)

    float *Qd, *Kd, *Vd, *QPd, *KPd, *AVd, *gd, *EWd;
    cudaGetSymbolAddress((void**)&Qd,  g_Q);
    cudaGetSymbolAddress((void**)&Kd,  g_K);
    cudaGetSymbolAddress((void**)&Vd,  g_V);
    cudaGetSymbolAddress((void**)&QPd, g_QP);
    cudaGetSymbolAddress((void**)&KPd, g_KP);
    cudaGetSymbolAddress((void**)&AVd, g_AV);
    cudaGetSymbolAddress((void**)&gd,  g_g);
    cudaGetSymbolAddress((void**)&EWd, g_EW);

    Proj5 p;
    p.A[0] = query; p.W[0] = wq_w;    p.bias[0] = wq_b;    p.C[0] = Qd;
    p.A[1] = key;   p.W[1] = wk_w;    p.bias[1] = wk_b;    p.C[1] = Kd;
    p.A[2] = value; p.W[2] = wv_w;    p.bias[2] = wv_b;    p.C[2] = Vd;
    p.A[3] = query; p.W[3] = mp_wq_w; p.bias[3] = mp_wq_b; p.C[3] = QPd;
    p.A[4] = key;   p.W[4] = mp_wk_w; p.bias[4] = mp_wk_b; p.C[4] = KPd;

    proj5_kernel<<<dim3(D_ / 128, (B_ * L_) / 128, 5), 256>>>(p);

    gate_kernel<<<(B_ * L_) / 8, 256>>>(query, gate_w, gate_b, gd);

    m_kernel<<<dim3(L_ / 128, L_ / 128, B_), 256>>>(QPd, KPd, mout, EWd);

    cudaFuncSetAttribute(attn_kernel,
                         cudaFuncAttributeMaxDynamicSharedMemorySize,
                         ATTN_SMEM_BYTES);
    attn_kernel<<<dim3(L_ / 32, H_, B_), 256, ATTN_SMEM_BYTES>>>(
        Qd, Kd, Vd, EWd, gd, AVd);

    dense_kernel<<<dim3(D_ / 128, (B_ * L_) / 128), 256>>>(AVd, dense_w, dense_b, out);
}